// round 6
// baseline (speedup 1.0000x reference)
#include <cuda_runtime.h>

#define BSZ   8
#define NPTS  4096
#define CIN   128
#define COUT  256
#define MCTR  1024
#define SSAMP 64

// Scratch (static device globals: no allocations allowed)
__device__ float g_pre[BSZ * NPTS * COUT];   // [b][n][o]  33.5 MB
__device__ int   g_fps[BSZ * MCTR];
__device__ int   g_idx[BSZ * MCTR * SSAMP];

// Exact reference arithmetic: squares then left-to-right sum, no FMA contraction.
__device__ __forceinline__ float d2_rn(float ax, float ay, float az,
                                       float bx, float by, float bz) {
    float dx = ax - bx, dy = ay - by, dz = az - bz;
    return __fadd_rn(__fadd_rn(__fmul_rn(dx, dx), __fmul_rn(dy, dy)),
                     __fmul_rn(dz, dz));
}

// ---- packed f32x2 helpers (per-lane IEEE rn: bit-identical to scalar) ----
__device__ __forceinline__ unsigned long long pack2(float lo, float hi) {
    unsigned long long r;
    asm("mov.b64 %0, {%1, %2};" : "=l"(r) : "f"(lo), "f"(hi));
    return r;
}
__device__ __forceinline__ void unpack2(unsigned long long v, float& lo, float& hi) {
    asm("mov.b64 {%0, %1}, %2;" : "=f"(lo), "=f"(hi) : "l"(v));
}
__device__ __forceinline__ unsigned long long add2(unsigned long long a,
                                                   unsigned long long b) {
    unsigned long long r;
    asm("add.rn.f32x2 %0, %1, %2;" : "=l"(r) : "l"(a), "l"(b));
    return r;
}
__device__ __forceinline__ unsigned long long mul2(unsigned long long a,
                                                   unsigned long long b) {
    unsigned long long r;
    asm("mul.rn.f32x2 %0, %1, %2;" : "=l"(r) : "l"(a), "l"(b));
    return r;
}

// ---------------------------------------------------------------------------
// FPS: 512 threads x 8 points (4 packed f32x2 pairs per thread).
// Per iteration: packed distances, scalar FMNMX mind update (ALU pipe),
// scalar max-tree, warp REDUX(value) + predicated lowest-index rescan +
// REDUX(min idx); warp leaders store (val,idx) into a parity double-buffered
// 16-slot array; ONE __syncthreads; every warp redundantly reduces the 16
// winners so all threads learn Iv — no second barrier, no atomics, no resets.
// Winner coords re-read from global (L1-resident broadcast).
// dx = px + (-lx) is bit-identical to px - lx.
// ---------------------------------------------------------------------------
__device__ void fps_body(const float* __restrict__ xyz, int b) {
    const int tid = threadIdx.x;
    const int lane = tid & 31, warp = tid >> 5;   // 16 warps

    __shared__ int s_val[2][16];
    __shared__ int s_idx[2][16];

    const float* p = xyz + b * NPTS * 3;

    unsigned long long px2[4], py2[4], pz2[4];
    float mind[8];
#pragma unroll
    for (int j = 0; j < 4; j++) {
        int n0 = (2 * j) * 512 + tid;
        int n1 = (2 * j + 1) * 512 + tid;
        px2[j] = pack2(p[3 * n0 + 0], p[3 * n1 + 0]);
        py2[j] = pack2(p[3 * n0 + 1], p[3 * n1 + 1]);
        pz2[j] = pack2(p[3 * n0 + 2], p[3 * n1 + 2]);
        mind[2 * j] = 1e10f; mind[2 * j + 1] = 1e10f;
    }
    if (tid == 0) g_fps[b * MCTR] = 0;
    int Iv = 0;

    for (int t = 1; t < MCTR; t++) {
        const float lx = __ldg(p + 3 * Iv + 0);
        const float ly = __ldg(p + 3 * Iv + 1);
        const float lz = __ldg(p + 3 * Iv + 2);
        const unsigned long long nlx2 = pack2(-lx, -lx);
        const unsigned long long nly2 = pack2(-ly, -ly);
        const unsigned long long nlz2 = pack2(-lz, -lz);

#pragma unroll
        for (int j = 0; j < 4; j++) {
            unsigned long long dx2 = add2(px2[j], nlx2);
            unsigned long long dy2 = add2(py2[j], nly2);
            unsigned long long dz2 = add2(pz2[j], nlz2);
            unsigned long long s2 = add2(add2(mul2(dx2, dx2), mul2(dy2, dy2)),
                                         mul2(dz2, dz2));
            float s0, s1; unpack2(s2, s0, s1);
            mind[2 * j]     = fminf(mind[2 * j],     s0);
            mind[2 * j + 1] = fminf(mind[2 * j + 1], s1);
        }

        // scalar max tree (all values >= 0 -> int bit order == value order)
        float m01 = fmaxf(mind[0], mind[1]), m23 = fmaxf(mind[2], mind[3]);
        float m45 = fmaxf(mind[4], mind[5]), m67 = fmaxf(mind[6], mind[7]);
        float best = fmaxf(fmaxf(m01, m23), fmaxf(m45, m67));

        const int tb   = __float_as_int(best);
        const int wmax = __reduce_max_sync(0xffffffffu, tb);

        int n = 0x7fffffff;
        if (tb == wmax) {   // rare; predicated rescan, descending k -> lowest n
#pragma unroll
            for (int k = 7; k >= 0; k--)
                if (__float_as_int(mind[k]) == wmax) n = k * 512 + tid;
        }
        const int widx = __reduce_min_sync(0xffffffffu, n);

        if (lane == 0) { s_val[t & 1][warp] = wmax; s_idx[t & 1][warp] = widx; }
        __syncthreads();

        // every warp redundantly reduces the 16 warp winners
        int vb = (lane < 16) ? s_val[t & 1][lane] : (int)0x80000000;
        int vi = (lane < 16) ? s_idx[t & 1][lane] : 0x7fffffff;
        const int bmax = __reduce_max_sync(0xffffffffu, vb);
        int cand = (vb == bmax) ? vi : 0x7fffffff;
        Iv = __reduce_min_sync(0xffffffffu, cand);

        if (tid == 0) g_fps[b * MCTR + t] = Iv;
    }
}

// ---------------------------------------------------------------------------
// GEMM body (512 threads): pre[b][n][o] = sum_c feat[b][c][n] * W[o][c].
// Tile 64n x 128o, K-chunks of 32, 2x8 microtile. Pads: sF row 66 floats so
// the fv pair is 8B-aligned (LDS.64); sW row 132 so wv is a uniform LDS.128.
// ---------------------------------------------------------------------------
__device__ void gemm_body(const float* __restrict__ feat,
                          const float* __restrict__ W, int gid) {
    const int b    = gid >> 7;
    const int rest = gid & 127;
    const int o0   = (rest & 1) * 128;
    const int n0   = (rest >> 1) * 64;

    __shared__ float sF[32][66];
    __shared__ float sW[32][132];

    const int tid = threadIdx.x;
    const int tx = tid & 31;            // n pair
    const int ty = tid >> 5;            // o group of 8 (uniform per warp)

    float acc[2][8];
#pragma unroll
    for (int i = 0; i < 2; i++)
#pragma unroll
        for (int j = 0; j < 8; j++) acc[i][j] = 0.f;

    const float* fb = feat + b * CIN * NPTS;

    for (int k0 = 0; k0 < CIN; k0 += 32) {
#pragma unroll
        for (int i = 0; i < 4; i++) {       // 32x64 feat tile
            int e = tid + i * 512;
            sF[e >> 6][e & 63] = fb[(k0 + (e >> 6)) * NPTS + n0 + (e & 63)];
        }
#pragma unroll
        for (int i = 0; i < 8; i++) {       // 128o x 32c W tile, stored [c][o]
            int e = tid + i * 512;
            sW[e & 31][e >> 5] = W[(o0 + (e >> 5)) * CIN + k0 + (e & 31)];
        }
        __syncthreads();
#pragma unroll
        for (int c = 0; c < 32; c++) {
            float fv0 = sF[c][tx * 2 + 0];
            float fv1 = sF[c][tx * 2 + 1];
            float wv[8];
#pragma unroll
            for (int j = 0; j < 8; j++) wv[j] = sW[c][ty * 8 + j];
#pragma unroll
            for (int j = 0; j < 8; j++) {
                acc[0][j] += fv0 * wv[j];
                acc[1][j] += fv1 * wv[j];
            }
        }
        __syncthreads();
    }

    float* pb = g_pre + b * NPTS * COUT;
#pragma unroll
    for (int i = 0; i < 2; i++) {
        int n = n0 + tx * 2 + i;
#pragma unroll
        for (int j = 0; j < 8; j++)
            pb[n * COUT + o0 + ty * 8 + j] = acc[i][j];
    }
}

// ---------------------------------------------------------------------------
// Fused launch: blocks 0..7 -> FPS (one per batch), blocks 8..1031 -> GEMM.
// ---------------------------------------------------------------------------
__global__ __launch_bounds__(512) void fused_fps_gemm_kernel(
    const float* __restrict__ xyz, const float* __restrict__ feat,
    const float* __restrict__ W) {
    if (blockIdx.x < BSZ) fps_body(xyz, blockIdx.x);
    else                  gemm_body(feat, W, blockIdx.x - BSZ);
}

// ---------------------------------------------------------------------------
// Ball query: one warp per (b,m) center. Ballot-ordered ascending scan,
// early exit at 64 found, pad with first in-ball index.
// ---------------------------------------------------------------------------
__global__ __launch_bounds__(256) void ballquery_kernel(const float* __restrict__ xyz) {
    const int tid = threadIdx.x, lane = tid & 31, w = tid >> 5;
    const int gw = blockIdx.x * 8 + w;
    const int b = gw >> 10, m = gw & (MCTR - 1);
    const float* p = xyz + b * NPTS * 3;

    const int ci = g_fps[b * MCTR + m];
    const float cx = p[3 * ci + 0], cy = p[3 * ci + 1], cz = p[3 * ci + 2];
    const float R2 = 0.1024f;

    int cnt = 0, firstIdx = 0;
    int* dst = g_idx + (b * MCTR + m) * SSAMP;

    for (int c0 = 0; c0 < NPTS && cnt < SSAMP; c0 += 32) {
        int n = c0 + lane;
        float d = d2_rn(p[3 * n + 0], p[3 * n + 1], p[3 * n + 2], cx, cy, cz);
        bool in = d < R2;
        unsigned msk = __ballot_sync(0xffffffffu, in);
        if (cnt == 0 && msk) firstIdx = c0 + (__ffs(msk) - 1);
        if (in) {
            int pos = cnt + __popc(msk & ((1u << lane) - 1u));
            if (pos < SSAMP) dst[pos] = n;
        }
        cnt += __popc(msk);
    }
    for (int pos = cnt + lane; pos < SSAMP; pos += 32) dst[pos] = firstIdx;
}

// ---------------------------------------------------------------------------
// Max-gather + folded BN/bias/ReLU. 64 threads/block, float4 per thread,
// fully coalesced 16B loads.
// ---------------------------------------------------------------------------
__global__ __launch_bounds__(64) void maxpool_kernel(
    const float* __restrict__ bconv, const float* __restrict__ gamma,
    const float* __restrict__ beta,  const float* __restrict__ rmean,
    const float* __restrict__ rvar,  float* __restrict__ out) {
    const int m = blockIdx.x, b = blockIdx.y, tid = threadIdx.x;

    __shared__ int soff[SSAMP];
    soff[tid] = g_idx[(b * MCTR + m) * SSAMP + tid] * COUT;
    __syncthreads();

    const float* pb = g_pre + b * NPTS * COUT + tid * 4;
    float4 mx = make_float4(-3.4e38f, -3.4e38f, -3.4e38f, -3.4e38f);
#pragma unroll 8
    for (int s = 0; s < SSAMP; s++) {
        const float4 v = *(const float4*)(pb + soff[s]);
        mx.x = fmaxf(mx.x, v.x); mx.y = fmaxf(mx.y, v.y);
        mx.z = fmaxf(mx.z, v.z); mx.w = fmaxf(mx.w, v.w);
    }

    const float4 bc = ((const float4*)bconv)[tid];
    const float4 gm = ((const float4*)gamma)[tid];
    const float4 bt = ((const float4*)beta )[tid];
    const float4 rm = ((const float4*)rmean)[tid];
    const float4 rv = ((const float4*)rvar )[tid];

    const int o = tid * 4;
    out[(b * COUT + o + 0) * MCTR + m] =
        fmaxf((mx.x + bc.x - rm.x) * (gm.x * rsqrtf(rv.x + 1e-5f)) + bt.x, 0.f);
    out[(b * COUT + o + 1) * MCTR + m] =
        fmaxf((mx.y + bc.y - rm.y) * (gm.y * rsqrtf(rv.y + 1e-5f)) + bt.y, 0.f);
    out[(b * COUT + o + 2) * MCTR + m] =
        fmaxf((mx.z + bc.z - rm.z) * (gm.z * rsqrtf(rv.z + 1e-5f)) + bt.z, 0.f);
    out[(b * COUT + o + 3) * MCTR + m] =
        fmaxf((mx.w + bc.w - rm.w) * (gm.w * rsqrtf(rv.w + 1e-5f)) + bt.w, 0.f);
}

// ---------------------------------------------------------------------------
extern "C" void kernel_launch(void* const* d_in, const int* in_sizes, int n_in,
                              void* d_out, int out_size) {
    const float* xyz  = (const float*)d_in[0];
    const float* feat = (const float*)d_in[1];
    const float* W    = (const float*)d_in[2];
    const float* bcv  = (const float*)d_in[3];
    const float* gm   = (const float*)d_in[4];
    const float* bt   = (const float*)d_in[5];
    const float* rm   = (const float*)d_in[6];
    const float* rv   = (const float*)d_in[7];
    float* out = (float*)d_out;

    const int gemm_blocks = (NPTS / 64) * (COUT / 128) * BSZ;  // 1024
    fused_fps_gemm_kernel<<<BSZ + gemm_blocks, 512>>>(xyz, feat, W);
    ballquery_kernel<<<(BSZ * MCTR) / 8, 256>>>(xyz);
    maxpool_kernel<<<dim3(MCTR, BSZ), 64>>>(bcv, gm, bt, rm, rv, out);
}